// round 8
// baseline (speedup 1.0000x reference)
#include <cuda_runtime.h>
#include <cuda_bf16.h>
#include <math.h>

// Problem constants
#define BQ   128
#define TQ   256
#define INQ  128
#define HQ   1024
#define NCTA 128      // 32 col-tiles x 4 K-splits; all co-resident
#define NTHR 320      // 8 MMA warps (256 thr) + 2 cell warps (64 thr)
#define MMAT 256

#define NU0  36       // layer0 units of k32: 4 (x) + 32 (h0)
#define TILE16K 16384u
#define NBUF 4        // bulk pipeline depth (4 x 32KB stage)

// ---------------------------------------------------------------------------
// Device globals. Operand tiles contiguous + pre-swizzled: one cp.async.bulk
// per (A,W) per k32 unit. Tile (16KB) = [hi 8KB | lo 8KB]; within 8KB:
// byte off = r*64 + ((seg ^ ((r>>1)&3))<<4) + (k&7)*2,  seg = k>>3.
// ---------------------------------------------------------------------------
__device__ __align__(1024) unsigned char g_W0t[32u * NU0 * TILE16K];
__device__ __align__(1024) unsigned char g_W1t[32u * 64u * TILE16K];
__device__ __align__(1024) unsigned char g_xt[(unsigned)TQ * 4u * TILE16K];
__device__ __align__(1024) unsigned char g_h0t[32u * TILE16K];
__device__ __align__(1024) unsigned char g_h1t[32u * TILE16K];
__device__ float g_h1f[BQ * HQ];
__device__ float g_c0[BQ * HQ];
__device__ float g_c1[BQ * HQ];
// Partial gate sums: layer0 4 slots, layer1 8 slots (two phase-halves)
__device__ float g_part0[4u * 32u * 128u * 128u];
__device__ float g_part1[8u * 32u * 128u * 128u];

__device__ unsigned g_bar_count = 0;
__device__ unsigned g_bar_gen   = 0;

__device__ __forceinline__ unsigned off_in_tile(int r, int k) {
    return (unsigned)(r * 64 + ((((k >> 3) ^ ((r >> 1) & 3))) << 4) + ((k & 7) << 1));
}

// ---------------------------------------------------------------------------
// PTX helpers (sm_90 baseline — no 'a'-gated features)
// ---------------------------------------------------------------------------
__device__ __forceinline__ unsigned smem_u32(const void* p) {
    unsigned a;
    asm("{ .reg .u64 t; cvta.to.shared.u64 t, %1; cvt.u32.u64 %0, t; }"
        : "=r"(a) : "l"(p));
    return a;
}
__device__ __forceinline__ void mbar_init(unsigned mbar, unsigned cnt) {
    asm volatile("mbarrier.init.shared.b64 [%0], %1;" :: "r"(mbar), "r"(cnt) : "memory");
}
__device__ __forceinline__ void mbar_wait(unsigned mbar, unsigned parity) {
    asm volatile(
        "{\n\t.reg .pred P;\n\t"
        "W_%=:\n\t"
        "mbarrier.try_wait.parity.acquire.cta.shared::cta.b64 P, [%0], %1, 0x989680;\n\t"
        "@!P bra W_%=;\n\t}"
        :: "r"(mbar), "r"(parity) : "memory");
}
__device__ __forceinline__ void mbar_expect_tx(unsigned mbar, unsigned bytes) {
    asm volatile("mbarrier.arrive.expect_tx.shared.b64 _, [%0], %1;"
                 :: "r"(mbar), "r"(bytes) : "memory");
}
__device__ __forceinline__ void bulk_g2s(unsigned dst, const void* src,
                                         unsigned bytes, unsigned mbar) {
    asm volatile(
        "cp.async.bulk.shared::cluster.global.mbarrier::complete_tx::bytes "
        "[%0], [%1], %2, [%3];"
        :: "r"(dst), "l"(src), "r"(bytes), "r"(mbar) : "memory");
}
__device__ __forceinline__ void fence_async() {
    asm volatile("fence.proxy.async.shared::cta;" ::: "memory");
}
__device__ __forceinline__ void bar_mma() {   // named barrier, MMA warps only
    asm volatile("bar.sync 1, 256;" ::: "memory");
}
__device__ __forceinline__ void ldsm4(unsigned& r0, unsigned& r1,
                                      unsigned& r2, unsigned& r3, unsigned a) {
    asm volatile("ldmatrix.sync.aligned.m8n8.x4.shared.b16 {%0,%1,%2,%3}, [%4];"
                 : "=r"(r0), "=r"(r1), "=r"(r2), "=r"(r3) : "r"(a));
}
__device__ __forceinline__ void ldsm2(unsigned& r0, unsigned& r1, unsigned a) {
    asm volatile("ldmatrix.sync.aligned.m8n8.x2.shared.b16 {%0,%1}, [%2];"
                 : "=r"(r0), "=r"(r1) : "r"(a));
}
__device__ __forceinline__ void mma16816(float* d, const unsigned* a, const unsigned* b) {
    asm volatile(
        "mma.sync.aligned.m16n8k16.row.col.f32.bf16.bf16.f32 "
        "{%0,%1,%2,%3}, {%4,%5,%6,%7}, {%8,%9}, {%0,%1,%2,%3};"
        : "+f"(d[0]), "+f"(d[1]), "+f"(d[2]), "+f"(d[3])
        : "r"(a[0]), "r"(a[1]), "r"(a[2]), "r"(a[3]), "r"(b[0]), "r"(b[1]));
}

// ---------------------------------------------------------------------------
// Grid barrier (all NCTA CTAs co-resident)
// ---------------------------------------------------------------------------
__device__ __forceinline__ void grid_bar() {
    __syncthreads();
    if (threadIdx.x == 0) {
        __threadfence();
        unsigned my = *(volatile unsigned*)&g_bar_gen;
        if (atomicAdd(&g_bar_count, 1u) == NCTA - 1u) {
            *(volatile unsigned*)&g_bar_count = 0;
            __threadfence();
            atomicExch(&g_bar_gen, my + 1u);
        } else {
            while (*(volatile unsigned*)&g_bar_gen == my) { }
        }
        __threadfence();
    }
    __syncthreads();
}

// ---------------------------------------------------------------------------
// Init kernels (per replay; deterministic)
// ---------------------------------------------------------------------------
__device__ __forceinline__ void split_store(float v, unsigned char* hi_ptr) {
    __nv_bfloat16 h = __float2bfloat16(v);
    __nv_bfloat16 l = __float2bfloat16(v - __bfloat162float(h));
    *(__nv_bfloat16*)hi_ptr = h;
    *(__nv_bfloat16*)(hi_ptr + 8192) = l;
}

__global__ void init_state_kernel() {
    int i = blockIdx.x * blockDim.x + threadIdx.x;
    if (i < (32 * 16384) / 4) {
        ((unsigned*)g_h0t)[i] = 0u;
        ((unsigned*)g_h1t)[i] = 0u;
    }
    if (i < BQ * HQ) { g_c0[i] = 0.f; g_c1[i] = 0.f; }
}
__global__ void init_x_kernel(const float* __restrict__ x) {
    int i = blockIdx.x * blockDim.x + threadIdx.x;   // = b*32768 + t*128 + k
    if (i >= BQ * TQ * INQ) return;
    int k = i & 127, t = (i >> 7) & 255, b = i >> 15;
    int u = k >> 5, kl = k & 31;
    unsigned char* dst = g_xt + (size_t)(t * 4 + u) * TILE16K + off_in_tile(b, kl);
    split_store(x[i], dst);
}
__global__ void init_w_kernel(
    const float* __restrict__ W_ih0, const float* __restrict__ W_hh0,
    const float* __restrict__ W_ih1, const float* __restrict__ W_hh1)
{
    const unsigned N0 = 32u * NU0 * 4096u;
    const unsigned N1 = 32u * 64u * 4096u;
    for (unsigned i = blockIdx.x * blockDim.x + threadIdx.x; i < N0 + N1;
         i += gridDim.x * blockDim.x) {
        if (i < N0) {
            unsigned kl = i & 31u, r = (i >> 5) & 127u;
            unsigned rest = i >> 12, u = rest % NU0, tile = rest / NU0;
            unsigned gcol = ((r >> 5) << 10) + tile * 32u + (r & 31u);
            unsigned k = u * 32u + kl;
            float v = (k < 128u) ? W_ih0[(size_t)gcol * 128u + k]
                                 : W_hh0[(size_t)gcol * 1024u + (k - 128u)];
            split_store(v, g_W0t + (size_t)(tile * NU0 + u) * TILE16K + off_in_tile(r, kl));
        } else {
            unsigned j = i - N0;
            unsigned kl = j & 31u, r = (j >> 5) & 127u;
            unsigned rest = j >> 12, u = rest & 63u, tile = rest >> 6;
            unsigned gcol = ((r >> 5) << 10) + tile * 32u + (r & 31u);
            unsigned k = u * 32u + kl;
            float v = (k < 1024u) ? W_ih1[(size_t)gcol * 1024u + k]
                                  : W_hh1[(size_t)gcol * 1024u + (k - 1024u)];
            split_store(v, g_W1t + (size_t)(tile * 64u + u) * TILE16K + off_in_tile(r, kl));
        }
    }
}

// ---------------------------------------------------------------------------
// Cell phase: runs on the 2 cell warps (64 threads). Sums NS partial slots +
// biases; updates c; writes swizzled split-h tiles (and optional fp32 h).
// ---------------------------------------------------------------------------
template <int NS>
__device__ void cell_phase(
    float* __restrict__ cst, unsigned char* __restrict__ htile,
    float* __restrict__ hf, const float* __restrict__ part,
    const float* __restrict__ b_ih, const float* __restrict__ b_hh)
{
    const int ctid = threadIdx.x - MMAT;             // 0..63
    const int base = blockIdx.x * 64 + ctid;         // 0..8191
    #pragma unroll
    for (int it = 0; it < (BQ * HQ) / (NCTA * 64); ++it) {   // 16 iters
        int gid  = base + it * NCTA * 64;   // = b*1024 + n
        int n    = gid & 1023;
        int b    = gid >> 10;
        int tile = n >> 5, nl = n & 31;

        float g4[4];
        #pragma unroll
        for (int g = 0; g < 4; ++g) {
            float sum = b_ih[g * 1024 + n] + b_hh[g * 1024 + n];
            #pragma unroll
            for (int s2 = 0; s2 < NS; ++s2)
                sum += part[((size_t)(s2 * 32 + tile) << 14)
                            + (size_t)b * 128 + g * 32 + nl];
            g4[g] = sum;
        }
        float si = 1.f / (1.f + expf(-g4[0]));
        float sf = 1.f / (1.f + expf(-g4[1]));
        float so = 1.f / (1.f + expf(-g4[3]));
        float cn = sf * cst[gid] + si * tanhf(g4[2]);
        cst[gid] = cn;
        float hv = so * tanhf(cn);
        split_store(hv, htile + (size_t)tile * TILE16K + off_in_tile(b, nl));
        if (hf) hf[gid] = hv;
    }
}

// ---------------------------------------------------------------------------
// GEMM phase: runs on the 8 MMA warps (tid < 256). Per k32 unit: 2 bulk
// copies (A 16KB, W 16KB), mbarrier pipeline, 3-term split bf16 HMMA.
// Named barrier (256 thr) after the last ldmatrix of each unit gates the
// TMA refill of that buffer — MMA compute proceeds past it on registers.
// ---------------------------------------------------------------------------
__device__ void gemm_phase(
    const unsigned char* __restrict__ pxa, int uxsplit,
    const unsigned char* __restrict__ pha,
    const unsigned char* __restrict__ pw,
    int ulo, int nU, float* __restrict__ pslot,
    unsigned sb, unsigned* ph)
{
    const int tid  = threadIdx.x;
    const int lane = tid & 31;
    const int wid  = tid >> 5;
    const int wm   = wid >> 2;
    const int wn   = wid & 3;

    float acc[4][4][4];
    #pragma unroll
    for (int m = 0; m < 4; ++m)
        #pragma unroll
        for (int n = 0; n < 4; ++n)
            #pragma unroll
            for (int r = 0; r < 4; ++r) acc[m][n][r] = 0.f;

    auto issue = [&](int idx) {
        int u = ulo + idx;
        const unsigned char* asrc = (u < uxsplit)
            ? pxa + (size_t)u * TILE16K
            : pha + (size_t)(u - uxsplit) * TILE16K;
        const unsigned char* wsrc = pw + (size_t)u * TILE16K;
        int buf = idx & (NBUF - 1);
        unsigned mbar = sb + (unsigned)buf * 8u;
        unsigned dst  = sb + 1024u + (unsigned)buf * 32768u;
        mbar_expect_tx(mbar, 32768u);
        bulk_g2s(dst,           asrc, TILE16K, mbar);
        bulk_g2s(dst + TILE16K, wsrc, TILE16K, mbar);
    };

    if (tid == 0) {
        int np = nU < NBUF ? nU : NBUF;
        for (int p = 0; p < np; ++p) issue(p);
    }

    for (int i = 0; i < nU; ++i) {
        int buf = i & (NBUF - 1);
        mbar_wait(sb + (unsigned)buf * 8u, ph[buf]);
        ph[buf] ^= 1u;
        unsigned bA = sb + 1024u + (unsigned)buf * 32768u;   // A hi (lo +8192)
        unsigned bW = bA + TILE16K;                          // W hi (lo +8192)

        #pragma unroll
        for (int j = 0; j < 2; ++j) {
            int rA = wm * 64 + (lane & 15);
            unsigned aH = bA + (unsigned)(rA * 64)
                        + ((unsigned)((j * 2 + (lane >> 4)) ^ ((rA >> 1) & 3)) << 4);
            unsigned AH[4][4], AL[4][4];
            #pragma unroll
            for (int m = 0; m < 4; ++m) {
                ldsm4(AH[m][0], AH[m][1], AH[m][2], AH[m][3], aH + m * 1024u);
                ldsm4(AL[m][0], AL[m][1], AL[m][2], AL[m][3], aH + m * 1024u + 8192u);
            }
            int rW = wn * 32 + (lane & 7);
            unsigned wH = bW + (unsigned)(rW * 64)
                        + ((unsigned)((j * 2 + ((lane >> 3) & 1)) ^ ((rW >> 1) & 3)) << 4);
            unsigned WH[4][2], WL[4][2];
            #pragma unroll
            for (int n = 0; n < 4; ++n) {
                ldsm2(WH[n][0], WH[n][1], wH + n * 512u);
                ldsm2(WL[n][0], WL[n][1], wH + n * 512u + 8192u);
            }
            if (j == 1) {
                // All 256 MMA threads have consumed this buffer's SMEM.
                bar_mma();
                if (tid == 0 && i + NBUF < nU) issue(i + NBUF);
            }
            #pragma unroll
            for (int m = 0; m < 4; ++m)
                #pragma unroll
                for (int n = 0; n < 4; ++n) {
                    mma16816(acc[m][n], AH[m], WH[n]);
                    mma16816(acc[m][n], AL[m], WH[n]);
                    mma16816(acc[m][n], AH[m], WL[n]);
                }
        }
    }

    // Epilogue: D fragments -> pslot[b][c]
    #pragma unroll
    for (int m = 0; m < 4; ++m)
        #pragma unroll
        for (int n = 0; n < 4; ++n) {
            int b = wm * 64 + m * 16 + (lane >> 2);
            int c = wn * 32 + n * 8 + (lane & 3) * 2;
            *(float2*)(pslot + (size_t)b * 128 + c) =
                make_float2(acc[m][n][0], acc[m][n][1]);
            *(float2*)(pslot + (size_t)(b + 8) * 128 + c) =
                make_float2(acc[m][n][2], acc[m][n][3]);
        }
}

// ---------------------------------------------------------------------------
// Main persistent kernel: 3 phases per step; cells run on dedicated warps
// concurrently with the MMA warps of the same phase.
// ---------------------------------------------------------------------------
__global__ __launch_bounds__(NTHR, 1) void lstm_mma_kernel(
    const float* __restrict__ b_ih0, const float* __restrict__ b_hh0,
    const float* __restrict__ b_ih1, const float* __restrict__ b_hh1,
    const float* __restrict__ Wd,    const float* __restrict__ bd,
    float* __restrict__ out)
{
    extern __shared__ __align__(1024) unsigned char dsmem[];
    const unsigned sb = smem_u32(dsmem);
    const int tid  = threadIdx.x;
    const int cta  = blockIdx.x;
    const int tile = cta & 31;
    const int s    = cta >> 5;

    if (tid == 0) {
        #pragma unroll
        for (int i = 0; i < NBUF; ++i) mbar_init(sb + i * 8u, 1u);
        fence_async();
    }
    __syncthreads();

    unsigned ph[NBUF] = {0, 0, 0, 0};

    const unsigned char* w0 = g_W0t + (size_t)tile * NU0 * TILE16K;
    const unsigned char* w1 = g_W1t + (size_t)tile * 64u * TILE16K;
    float* p0slot  = g_part0 + ((size_t)(s * 32 + tile) << 14);
    float* p1aslot = g_part1 + ((size_t)(s * 32 + tile) << 14);
    float* p1bslot = g_part1 + ((size_t)((4 + s) * 32 + tile) << 14);

    for (int t = 0; t < TQ; ++t) {
        // P1: MMA: gemm0(t) [9 units: x(0-3), h0(4-35)]  ||  cell: cell1(t-1)
        if (tid < MMAT)
            gemm_phase(g_xt + (size_t)t * 4 * TILE16K, 4, g_h0t, w0,
                       s * 9, 9, p0slot, sb, ph);
        else if (t > 0)
            cell_phase<8>(g_c1, g_h1t, g_h1f, g_part1, b_ih1, b_hh1);
        grid_bar();

        // P2: MMA: gemm1 h1-half [units 32+s*8..+8, A = h1]  ||  cell: cell0(t)
        if (tid < MMAT)
            gemm_phase(nullptr, 32, g_h1t, w1,
                       32 + s * 8, 8, p1aslot, sb, ph);
        else
            cell_phase<4>(g_c0, g_h0t, nullptr, g_part0, b_ih0, b_hh0);
        grid_bar();

        // P3: MMA: gemm1 h0-half [units s*8..+8, A = h0]  ||  cell: idle
        if (tid < MMAT)
            gemm_phase(nullptr, 0, g_h0t, w1,
                       s * 8, 8, p1bslot, sb, ph);
        grid_bar();
    }

    // Final cell1(255) on the cell warps
    if (tid >= MMAT)
        cell_phase<8>(g_c1, g_h1t, g_h1f, g_part1, b_ih1, b_hh1);
    grid_bar();

    // Dense head: CTA b computes out[b][0..1] from fp32 h1 (10-warp reduce)
    {
        float* red = (float*)dsmem;
        const int b = cta;
        const int lane = tid & 31;
        const int wid  = tid >> 5;
        float s0 = 0.f, s1 = 0.f;
        for (int n = tid; n < HQ; n += NTHR) {
            float hv = g_h1f[(size_t)b * HQ + n];
            s0 += hv * Wd[n];
            s1 += hv * Wd[HQ + n];
        }
        #pragma unroll
        for (int off = 16; off > 0; off >>= 1) {
            s0 += __shfl_down_sync(0xffffffffu, s0, off);
            s1 += __shfl_down_sync(0xffffffffu, s1, off);
        }
        __syncthreads();   // dsmem no longer in use by TMA
        if (lane == 0) { red[wid] = s0; red[16 + wid] = s1; }
        __syncthreads();
        if (tid == 0) {
            float a0 = 0.f, a1 = 0.f;
            #pragma unroll
            for (int w = 0; w < NTHR / 32; ++w) { a0 += red[w]; a1 += red[16 + w]; }
            out[b * 2 + 0] = tanhf(a0 + bd[0]);
            out[b * 2 + 1] = tanhf(a1 + bd[1]);
        }
    }
}

// ---------------------------------------------------------------------------
// Launch: 4 graph nodes
// ---------------------------------------------------------------------------
extern "C" void kernel_launch(void* const* d_in, const int* in_sizes, int n_in,
                              void* d_out, int out_size)
{
    const float* x     = (const float*)d_in[0];
    const float* W_ih0 = (const float*)d_in[1];
    const float* W_hh0 = (const float*)d_in[2];
    const float* b_ih0 = (const float*)d_in[3];
    const float* b_hh0 = (const float*)d_in[4];
    const float* W_ih1 = (const float*)d_in[5];
    const float* W_hh1 = (const float*)d_in[6];
    const float* b_ih1 = (const float*)d_in[7];
    const float* b_hh1 = (const float*)d_in[8];
    const float* Wd    = (const float*)d_in[9];
    const float* bd    = (const float*)d_in[10];
    float* out = (float*)d_out;

    const int smem_bytes = 1024 + NBUF * 32768;   // 132096
    cudaFuncSetAttribute(lstm_mma_kernel,
                         cudaFuncAttributeMaxDynamicSharedMemorySize, smem_bytes);

    init_state_kernel<<<(32 * 16384 / 4 + 255) / 256, 256>>>();
    init_x_kernel<<<(BQ * TQ * INQ + 255) / 256, 256>>>(x);
    init_w_kernel<<<2048, 256>>>(W_ih0, W_hh0, W_ih1, W_hh1);

    lstm_mma_kernel<<<NCTA, NTHR, smem_bytes>>>(
        b_ih0, b_hh0, b_ih1, b_hh1, Wd, bd, out);
}

// round 9
// speedup vs baseline: 1.7344x; 1.7344x over previous
#include <cuda_runtime.h>
#include <cuda_bf16.h>
#include <math.h>

// Problem constants
#define BQ   128
#define TQ   256
#define INQ  128
#define HQ   1024
#define NCTA 128      // 32 col-tiles x 4 K-splits; all co-resident
#define NTHR 256

#define NU0  36       // layer0 units of k32: 4 (x) + 32 (h0)
#define TILE16K 16384u
#define NBUF 4        // bulk pipeline depth (4 x 32KB stage)

// ---------------------------------------------------------------------------
// Device globals. Operand tiles contiguous + pre-swizzled: one cp.async.bulk
// per (A,W) per k32 unit. Tile (16KB) = [hi 8KB | lo 8KB]; within 8KB:
// byte off = r*64 + ((seg ^ ((r>>1)&3))<<4) + (k&7)*2,  seg = k>>3.
// ---------------------------------------------------------------------------
__device__ __align__(1024) unsigned char g_W0t[32u * NU0 * TILE16K];
__device__ __align__(1024) unsigned char g_W1t[32u * 64u * TILE16K];
__device__ __align__(1024) unsigned char g_xt[(unsigned)TQ * 4u * TILE16K];
__device__ __align__(1024) unsigned char g_h0t[32u * TILE16K];
__device__ __align__(1024) unsigned char g_h1t[32u * TILE16K];
__device__ float g_h1f[BQ * HQ];
__device__ float g_c0[BQ * HQ];
__device__ float g_c1[BQ * HQ];
// Partial gate sums: layer0 4 slots, layer1 8 slots (two phase-halves)
__device__ float g_part0[4u * 32u * 128u * 128u];
__device__ float g_part1[8u * 32u * 128u * 128u];

__device__ unsigned g_bar_count = 0;
__device__ unsigned g_bar_gen   = 0;

__device__ __forceinline__ unsigned off_in_tile(int r, int k) {
    return (unsigned)(r * 64 + ((((k >> 3) ^ ((r >> 1) & 3))) << 4) + ((k & 7) << 1));
}

// ---------------------------------------------------------------------------
// PTX helpers (sm_90 baseline — no 'a'-gated features)
// ---------------------------------------------------------------------------
__device__ __forceinline__ unsigned smem_u32(const void* p) {
    unsigned a;
    asm("{ .reg .u64 t; cvta.to.shared.u64 t, %1; cvt.u32.u64 %0, t; }"
        : "=r"(a) : "l"(p));
    return a;
}
__device__ __forceinline__ void mbar_init(unsigned mbar, unsigned cnt) {
    asm volatile("mbarrier.init.shared.b64 [%0], %1;" :: "r"(mbar), "r"(cnt) : "memory");
}
__device__ __forceinline__ void mbar_wait(unsigned mbar, unsigned parity) {
    asm volatile(
        "{\n\t.reg .pred P;\n\t"
        "W_%=:\n\t"
        "mbarrier.try_wait.parity.acquire.cta.shared::cta.b64 P, [%0], %1, 0x989680;\n\t"
        "@!P bra W_%=;\n\t}"
        :: "r"(mbar), "r"(parity) : "memory");
}
__device__ __forceinline__ void mbar_expect_tx(unsigned mbar, unsigned bytes) {
    asm volatile("mbarrier.arrive.expect_tx.shared.b64 _, [%0], %1;"
                 :: "r"(mbar), "r"(bytes) : "memory");
}
__device__ __forceinline__ void bulk_g2s(unsigned dst, const void* src,
                                         unsigned bytes, unsigned mbar) {
    asm volatile(
        "cp.async.bulk.shared::cluster.global.mbarrier::complete_tx::bytes "
        "[%0], [%1], %2, [%3];"
        :: "r"(dst), "l"(src), "r"(bytes), "r"(mbar) : "memory");
}
__device__ __forceinline__ void fence_async() {
    asm volatile("fence.proxy.async.shared::cta;" ::: "memory");
}
__device__ __forceinline__ void ldsm4(unsigned& r0, unsigned& r1,
                                      unsigned& r2, unsigned& r3, unsigned a) {
    asm volatile("ldmatrix.sync.aligned.m8n8.x4.shared.b16 {%0,%1,%2,%3}, [%4];"
                 : "=r"(r0), "=r"(r1), "=r"(r2), "=r"(r3) : "r"(a));
}
__device__ __forceinline__ void mma16816(float* d, const unsigned* a, const unsigned* b) {
    asm volatile(
        "mma.sync.aligned.m16n8k16.row.col.f32.bf16.bf16.f32 "
        "{%0,%1,%2,%3}, {%4,%5,%6,%7}, {%8,%9}, {%0,%1,%2,%3};"
        : "+f"(d[0]), "+f"(d[1]), "+f"(d[2]), "+f"(d[3])
        : "r"(a[0]), "r"(a[1]), "r"(a[2]), "r"(a[3]), "r"(b[0]), "r"(b[1]));
}

// ---------------------------------------------------------------------------
// Grid barrier (all NCTA CTAs co-resident)
// ---------------------------------------------------------------------------
__device__ __forceinline__ void grid_bar() {
    __syncthreads();
    if (threadIdx.x == 0) {
        __threadfence();
        unsigned my = *(volatile unsigned*)&g_bar_gen;
        if (atomicAdd(&g_bar_count, 1u) == NCTA - 1u) {
            *(volatile unsigned*)&g_bar_count = 0;
            __threadfence();
            atomicExch(&g_bar_gen, my + 1u);
        } else {
            while (*(volatile unsigned*)&g_bar_gen == my) { }
        }
        __threadfence();
    }
    __syncthreads();
}

// ---------------------------------------------------------------------------
// Init kernels (per replay; deterministic)
// ---------------------------------------------------------------------------
__device__ __forceinline__ void split_store(float v, unsigned char* hi_ptr) {
    __nv_bfloat16 h = __float2bfloat16(v);
    __nv_bfloat16 l = __float2bfloat16(v - __bfloat162float(h));
    *(__nv_bfloat16*)hi_ptr = h;
    *(__nv_bfloat16*)(hi_ptr + 8192) = l;
}

__global__ void init_state_kernel() {
    int i = blockIdx.x * blockDim.x + threadIdx.x;
    if (i < (32 * 16384) / 4) {
        ((unsigned*)g_h0t)[i] = 0u;
        ((unsigned*)g_h1t)[i] = 0u;
    }
    if (i < BQ * HQ) { g_c0[i] = 0.f; g_c1[i] = 0.f; }
}
__global__ void init_x_kernel(const float* __restrict__ x) {
    int i = blockIdx.x * blockDim.x + threadIdx.x;   // = b*32768 + t*128 + k
    if (i >= BQ * TQ * INQ) return;
    int k = i & 127, t = (i >> 7) & 255, b = i >> 15;
    int u = k >> 5, kl = k & 31;
    unsigned char* dst = g_xt + (size_t)(t * 4 + u) * TILE16K + off_in_tile(b, kl);
    split_store(x[i], dst);
}
__global__ void init_w_kernel(
    const float* __restrict__ W_ih0, const float* __restrict__ W_hh0,
    const float* __restrict__ W_ih1, const float* __restrict__ W_hh1)
{
    const unsigned N0 = 32u * NU0 * 4096u;
    const unsigned N1 = 32u * 64u * 4096u;
    for (unsigned i = blockIdx.x * blockDim.x + threadIdx.x; i < N0 + N1;
         i += gridDim.x * blockDim.x) {
        if (i < N0) {
            unsigned kl = i & 31u, r = (i >> 5) & 127u;
            unsigned rest = i >> 12, u = rest % NU0, tile = rest / NU0;
            unsigned gcol = ((r >> 5) << 10) + tile * 32u + (r & 31u);
            unsigned k = u * 32u + kl;
            float v = (k < 128u) ? W_ih0[(size_t)gcol * 128u + k]
                                 : W_hh0[(size_t)gcol * 1024u + (k - 128u)];
            split_store(v, g_W0t + (size_t)(tile * NU0 + u) * TILE16K + off_in_tile(r, kl));
        } else {
            unsigned j = i - N0;
            unsigned kl = j & 31u, r = (j >> 5) & 127u;
            unsigned rest = j >> 12, u = rest & 63u, tile = rest >> 6;
            unsigned gcol = ((r >> 5) << 10) + tile * 32u + (r & 31u);
            unsigned k = u * 32u + kl;
            float v = (k < 1024u) ? W_ih1[(size_t)gcol * 1024u + k]
                                  : W_hh1[(size_t)gcol * 1024u + (k - 1024u)];
            split_store(v, g_W1t + (size_t)(tile * 64u + u) * TILE16K + off_in_tile(r, kl));
        }
    }
}

// ---------------------------------------------------------------------------
// One cell-slice (1/4 of the cell update) on all 256 threads.
// NS = number of partial slots to sum. Writes c, swizzled split-h, opt fp32 h.
// ---------------------------------------------------------------------------
template <int NS>
__device__ __forceinline__ void cell_slice(
    int it, float* __restrict__ cst, unsigned char* __restrict__ htile,
    float* __restrict__ hf, const float* __restrict__ part,
    const float* __restrict__ b_ih, const float* __restrict__ b_hh)
{
    int gid  = blockIdx.x * NTHR + threadIdx.x + it * NCTA * NTHR;  // b*1024+n
    int n    = gid & 1023;
    int b    = gid >> 10;
    int tile = n >> 5, nl = n & 31;

    float g4[4];
    #pragma unroll
    for (int g = 0; g < 4; ++g) {
        float sum = b_ih[g * 1024 + n] + b_hh[g * 1024 + n];
        #pragma unroll
        for (int s2 = 0; s2 < NS; ++s2)
            sum += part[((size_t)(s2 * 32 + tile) << 14)
                        + (size_t)b * 128 + g * 32 + nl];
        g4[g] = sum;
    }
    float si = 1.f / (1.f + expf(-g4[0]));
    float sf = 1.f / (1.f + expf(-g4[1]));
    float so = 1.f / (1.f + expf(-g4[3]));
    float cn = sf * cst[gid] + si * tanhf(g4[2]);
    cst[gid] = cn;
    float hv = so * tanhf(cn);
    split_store(hv, htile + (size_t)tile * TILE16K + off_in_tile(b, nl));
    if (hf) hf[gid] = hv;
}

// ---------------------------------------------------------------------------
// GEMM phase. Per k32 unit: 2 bulk copies (A 16KB, W 16KB), mbarrier pipeline,
// 3-term split bf16 HMMA with TERM-OUTER ordering (16 independent accs between
// same-acc reuses). W fragments fetched as ldsm4 pairs. Cell work (CELLK: 0
// none, 1 cell0, 2 cell1) interleaved as slices after units 0,2,4,6 — their
// L2 loads drain while the queued HMMAs of the unit execute.
// ---------------------------------------------------------------------------
template <int CELLK>
__device__ void gemm_phase(
    const unsigned char* __restrict__ pxa, int uxsplit,
    const unsigned char* __restrict__ pha,
    const unsigned char* __restrict__ pw,
    int ulo, int nU, float* __restrict__ pslot,
    unsigned sb, unsigned* ph, bool docell,
    const float* b_ih, const float* b_hh)
{
    const int tid  = threadIdx.x;
    const int lane = tid & 31;
    const int wid  = tid >> 5;
    const int wm   = wid >> 2;
    const int wn   = wid & 3;

    float acc[4][4][4];
    #pragma unroll
    for (int m = 0; m < 4; ++m)
        #pragma unroll
        for (int n = 0; n < 4; ++n)
            #pragma unroll
            for (int r = 0; r < 4; ++r) acc[m][n][r] = 0.f;

    auto issue = [&](int idx) {
        int u = ulo + idx;
        const unsigned char* asrc = (u < uxsplit)
            ? pxa + (size_t)u * TILE16K
            : pha + (size_t)(u - uxsplit) * TILE16K;
        const unsigned char* wsrc = pw + (size_t)u * TILE16K;
        int buf = idx & (NBUF - 1);
        unsigned mbar = sb + (unsigned)buf * 8u;
        unsigned dst  = sb + 1024u + (unsigned)buf * 32768u;
        mbar_expect_tx(mbar, 32768u);
        bulk_g2s(dst,           asrc, TILE16K, mbar);
        bulk_g2s(dst + TILE16K, wsrc, TILE16K, mbar);
    };

    if (tid == 0) {
        int np = nU < NBUF ? nU : NBUF;
        for (int p = 0; p < np; ++p) issue(p);
    }

    for (int i = 0; i < nU; ++i) {
        int buf = i & (NBUF - 1);
        mbar_wait(sb + (unsigned)buf * 8u, ph[buf]);
        ph[buf] ^= 1u;
        unsigned bA = sb + 1024u + (unsigned)buf * 32768u;   // A hi (lo +8192)
        unsigned bW = bA + TILE16K;                          // W hi (lo +8192)

        #pragma unroll
        for (int j = 0; j < 2; ++j) {
            // A fragments: 4 m-tiles x (hi,lo), ldsm4 each
            int rA = wm * 64 + (lane & 15);
            unsigned aH = bA + (unsigned)(rA * 64)
                        + ((unsigned)((j * 2 + (lane >> 4)) ^ ((rA >> 1) & 3)) << 4);
            unsigned AH[4][4], AL[4][4];
            #pragma unroll
            for (int m = 0; m < 4; ++m) {
                ldsm4(AH[m][0], AH[m][1], AH[m][2], AH[m][3], aH + m * 1024u);
                ldsm4(AL[m][0], AL[m][1], AL[m][2], AL[m][3], aH + m * 1024u + 8192u);
            }
            // W fragments: 2 ldsm4 per (hi,lo), each covering an n-pair:
            // matrices = (n, k0),(n, k8),(n+1, k0),(n+1, k8)
            unsigned WH[4][2], WL[4][2];
            #pragma unroll
            for (int np = 0; np < 2; ++np) {
                int nn = np * 2 + (lane >> 4);           // n-tile for this lane
                int rW = wn * 32 + nn * 8 + (lane & 7);
                unsigned wAddr = bW + (unsigned)(rW * 64)
                    + ((unsigned)((j * 2 + ((lane >> 3) & 1)) ^ ((rW >> 1) & 3)) << 4);
                ldsm4(WH[np*2][0], WH[np*2][1], WH[np*2+1][0], WH[np*2+1][1], wAddr);
                ldsm4(WL[np*2][0], WL[np*2][1], WL[np*2+1][0], WL[np*2+1][1],
                      wAddr + 8192u);
            }
            if (j == 1) {
                __syncthreads();     // all threads done reading this buffer
                if (tid == 0 && i + NBUF < nU) issue(i + NBUF);
            }
            // Term-outer MMA: consecutive MMAs always hit different accs
            #pragma unroll
            for (int m = 0; m < 4; ++m)
                #pragma unroll
                for (int n = 0; n < 4; ++n)
                    mma16816(acc[m][n], AH[m], WH[n]);
            #pragma unroll
            for (int m = 0; m < 4; ++m)
                #pragma unroll
                for (int n = 0; n < 4; ++n)
                    mma16816(acc[m][n], AL[m], WH[n]);
            #pragma unroll
            for (int m = 0; m < 4; ++m)
                #pragma unroll
                for (int n = 0; n < 4; ++n)
                    mma16816(acc[m][n], AH[m], WL[n]);
        }

        // Interleaved cell slice: loads drain while this unit's HMMAs execute
        if (CELLK == 2 && docell && (i & 1) == 0 && i < 8)
            cell_slice<8>(i >> 1, g_c1, g_h1t, g_h1f, g_part1, b_ih, b_hh);
        else if (CELLK == 1 && docell && (i & 1) == 0 && i < 8)
            cell_slice<4>(i >> 1, g_c0, g_h0t, nullptr, g_part0, b_ih, b_hh);
    }

    // Epilogue: D fragments -> pslot[b][c]
    #pragma unroll
    for (int m = 0; m < 4; ++m)
        #pragma unroll
        for (int n = 0; n < 4; ++n) {
            int b = wm * 64 + m * 16 + (lane >> 2);
            int c = wn * 32 + n * 8 + (lane & 3) * 2;
            *(float2*)(pslot + (size_t)b * 128 + c) =
                make_float2(acc[m][n][0], acc[m][n][1]);
            *(float2*)(pslot + (size_t)(b + 8) * 128 + c) =
                make_float2(acc[m][n][2], acc[m][n][3]);
        }
}

// ---------------------------------------------------------------------------
// Main persistent kernel: 3 phases per step; cell slices interleaved into the
// following gemm phase on all 256 threads.
// ---------------------------------------------------------------------------
__global__ __launch_bounds__(NTHR, 1) void lstm_mma_kernel(
    const float* __restrict__ b_ih0, const float* __restrict__ b_hh0,
    const float* __restrict__ b_ih1, const float* __restrict__ b_hh1,
    const float* __restrict__ Wd,    const float* __restrict__ bd,
    float* __restrict__ out)
{
    extern __shared__ __align__(1024) unsigned char dsmem[];
    const unsigned sb = smem_u32(dsmem);
    const int tid  = threadIdx.x;
    const int cta  = blockIdx.x;
    const int tile = cta & 31;
    const int s    = cta >> 5;

    if (tid == 0) {
        #pragma unroll
        for (int i = 0; i < NBUF; ++i) mbar_init(sb + i * 8u, 1u);
        fence_async();
    }
    __syncthreads();

    unsigned ph[NBUF] = {0, 0, 0, 0};

    const unsigned char* w0 = g_W0t + (size_t)tile * NU0 * TILE16K;
    const unsigned char* w1 = g_W1t + (size_t)tile * 64u * TILE16K;
    float* p0slot  = g_part0 + ((size_t)(s * 32 + tile) << 14);
    float* p1aslot = g_part1 + ((size_t)(s * 32 + tile) << 14);
    float* p1bslot = g_part1 + ((size_t)((4 + s) * 32 + tile) << 14);

    for (int t = 0; t < TQ; ++t) {
        // P1: gemm0(t) [9 units: x(0-3), h0(4-35)] + interleaved cell1(t-1)
        gemm_phase<2>(g_xt + (size_t)t * 4 * TILE16K, 4, g_h0t, w0,
                      s * 9, 9, p0slot, sb, ph, t > 0, b_ih1, b_hh1);
        grid_bar();

        // P2: gemm1 h1-half [units 32+s*8..+8, A = h1] + interleaved cell0(t)
        gemm_phase<1>(nullptr, 32, g_h1t, w1,
                      32 + s * 8, 8, p1aslot, sb, ph, true, b_ih0, b_hh0);
        grid_bar();

        // P3: gemm1 h0-half [units s*8..+8, A = h0], no cell
        gemm_phase<0>(nullptr, 0, g_h0t, w1,
                      s * 8, 8, p1bslot, sb, ph, false, nullptr, nullptr);
        grid_bar();
    }

    // Final cell1(255) on all threads
    #pragma unroll
    for (int it = 0; it < 4; ++it)
        cell_slice<8>(it, g_c1, g_h1t, g_h1f, g_part1, b_ih1, b_hh1);
    grid_bar();

    // Dense head: CTA b computes out[b][0..1] from fp32 h1
    {
        float* red = (float*)dsmem;
        const int b = cta;
        float s0 = 0.f, s1 = 0.f;
        for (int n = tid; n < HQ; n += NTHR) {
            float hv = g_h1f[(size_t)b * HQ + n];
            s0 += hv * Wd[n];
            s1 += hv * Wd[HQ + n];
        }
        __syncthreads();
        red[tid] = s0; red[NTHR + tid] = s1;
        __syncthreads();
        for (int off = NTHR / 2; off > 0; off >>= 1) {
            if (tid < off) {
                red[tid] += red[tid + off];
                red[NTHR + tid] += red[NTHR + tid + off];
            }
            __syncthreads();
        }
        if (tid == 0) {
            out[b * 2 + 0] = tanhf(red[0] + bd[0]);
            out[b * 2 + 1] = tanhf(red[NTHR] + bd[1]);
        }
    }
}

// ---------------------------------------------------------------------------
// Launch: 4 graph nodes
// ---------------------------------------------------------------------------
extern "C" void kernel_launch(void* const* d_in, const int* in_sizes, int n_in,
                              void* d_out, int out_size)
{
    const float* x     = (const float*)d_in[0];
    const float* W_ih0 = (const float*)d_in[1];
    const float* W_hh0 = (const float*)d_in[2];
    const float* b_ih0 = (const float*)d_in[3];
    const float* b_hh0 = (const float*)d_in[4];
    const float* W_ih1 = (const float*)d_in[5];
    const float* W_hh1 = (const float*)d_in[6];
    const float* b_ih1 = (const float*)d_in[7];
    const float* b_hh1 = (const float*)d_in[8];
    const float* Wd    = (const float*)d_in[9];
    const float* bd    = (const float*)d_in[10];
    float* out = (float*)d_out;

    const int smem_bytes = 1024 + NBUF * 32768;   // 132096
    cudaFuncSetAttribute(lstm_mma_kernel,
                         cudaFuncAttributeMaxDynamicSharedMemorySize, smem_bytes);

    init_state_kernel<<<(32 * 16384 / 4 + 255) / 256, 256>>>();
    init_x_kernel<<<(BQ * TQ * INQ + 255) / 256, 256>>>(x);
    init_w_kernel<<<2048, 256>>>(W_ih0, W_hh0, W_ih1, W_hh1);

    lstm_mma_kernel<<<NCTA, NTHR, smem_bytes>>>(
        b_ih0, b_hh0, b_ih1, b_hh1, Wd, bd, out);
}

// round 10
// speedup vs baseline: 1.7527x; 1.0106x over previous
#include <cuda_runtime.h>
#include <cuda_bf16.h>
#include <math.h>

// Problem constants
#define BQ   128
#define TQ   256
#define INQ  128
#define HQ   1024
#define NCTA 256      // 64 col-tiles x 4 K-splits; 2 CTAs/SM co-resident
#define NTHR 128      // 4 MMA warps

#define NU0  36       // layer0 units of k32: 4 (x) + 32 (h0)
#define TILE16K 16384u   // A tile: 128 rows x 32 k, hi 8KB + lo 8KB
#define TILEW   8192u    // W tile: 64 rows x 32 k, hi 4KB + lo 4KB
#define STAGEB  24576u   // A + W per unit
#define NBUF 4

// ---------------------------------------------------------------------------
// Device globals. Tiles contiguous + pre-swizzled; one cp.async.bulk per
// operand per unit. Within a hi/lo block:
// byte off = r*64 + ((seg ^ ((r>>1)&3))<<4) + (k&7)*2,  seg = k>>3.
// ---------------------------------------------------------------------------
__device__ __align__(1024) unsigned char g_W0t[64u * NU0 * TILEW];   // 18.9MB
__device__ __align__(1024) unsigned char g_W1t[64u * 64u * TILEW];   // 33.6MB
__device__ __align__(1024) unsigned char g_xt[(unsigned)TQ * 4u * TILE16K];
__device__ __align__(1024) unsigned char g_h0t[32u * TILE16K];
__device__ __align__(1024) unsigned char g_h1t[32u * TILE16K];
__device__ float g_h1f[BQ * HQ];
__device__ float g_c0[BQ * HQ];
__device__ float g_c1[BQ * HQ];
// Partial gate sums, coalesced layout: [slot][b][gate*1024 + n]
__device__ float g_part0[4u * 128u * 4096u];   // 8MB
__device__ float g_part1[8u * 128u * 4096u];   // 16MB

__device__ unsigned g_bar_count = 0;
__device__ unsigned g_bar_gen   = 0;

__device__ __forceinline__ unsigned off_in_tile(int r, int k) {
    return (unsigned)(r * 64 + ((((k >> 3) ^ ((r >> 1) & 3))) << 4) + ((k & 7) << 1));
}

// ---------------------------------------------------------------------------
// PTX helpers (sm_90 baseline — no 'a'-gated features)
// ---------------------------------------------------------------------------
__device__ __forceinline__ unsigned smem_u32(const void* p) {
    unsigned a;
    asm("{ .reg .u64 t; cvta.to.shared.u64 t, %1; cvt.u32.u64 %0, t; }"
        : "=r"(a) : "l"(p));
    return a;
}
__device__ __forceinline__ void mbar_init(unsigned mbar, unsigned cnt) {
    asm volatile("mbarrier.init.shared.b64 [%0], %1;" :: "r"(mbar), "r"(cnt) : "memory");
}
__device__ __forceinline__ void mbar_wait(unsigned mbar, unsigned parity) {
    asm volatile(
        "{\n\t.reg .pred P;\n\t"
        "W_%=:\n\t"
        "mbarrier.try_wait.parity.acquire.cta.shared::cta.b64 P, [%0], %1, 0x989680;\n\t"
        "@!P bra W_%=;\n\t}"
        :: "r"(mbar), "r"(parity) : "memory");
}
__device__ __forceinline__ void mbar_expect_tx(unsigned mbar, unsigned bytes) {
    asm volatile("mbarrier.arrive.expect_tx.shared.b64 _, [%0], %1;"
                 :: "r"(mbar), "r"(bytes) : "memory");
}
__device__ __forceinline__ void bulk_g2s(unsigned dst, const void* src,
                                         unsigned bytes, unsigned mbar) {
    asm volatile(
        "cp.async.bulk.shared::cluster.global.mbarrier::complete_tx::bytes "
        "[%0], [%1], %2, [%3];"
        :: "r"(dst), "l"(src), "r"(bytes), "r"(mbar) : "memory");
}
__device__ __forceinline__ void fence_async() {
    asm volatile("fence.proxy.async.shared::cta;" ::: "memory");
}
__device__ __forceinline__ void ldsm4(unsigned& r0, unsigned& r1,
                                      unsigned& r2, unsigned& r3, unsigned a) {
    asm volatile("ldmatrix.sync.aligned.m8n8.x4.shared.b16 {%0,%1,%2,%3}, [%4];"
                 : "=r"(r0), "=r"(r1), "=r"(r2), "=r"(r3) : "r"(a));
}
__device__ __forceinline__ void mma16816(float* d, const unsigned* a, const unsigned* b) {
    asm volatile(
        "mma.sync.aligned.m16n8k16.row.col.f32.bf16.bf16.f32 "
        "{%0,%1,%2,%3}, {%4,%5,%6,%7}, {%8,%9}, {%0,%1,%2,%3};"
        : "+f"(d[0]), "+f"(d[1]), "+f"(d[2]), "+f"(d[3])
        : "r"(a[0]), "r"(a[1]), "r"(a[2]), "r"(a[3]), "r"(b[0]), "r"(b[1]));
}

// ---------------------------------------------------------------------------
// Grid barrier (all NCTA CTAs co-resident: 2 per SM on 128 of 148 SMs)
// ---------------------------------------------------------------------------
__device__ __forceinline__ void grid_bar() {
    __syncthreads();
    if (threadIdx.x == 0) {
        __threadfence();
        unsigned my = *(volatile unsigned*)&g_bar_gen;
        if (atomicAdd(&g_bar_count, 1u) == NCTA - 1u) {
            *(volatile unsigned*)&g_bar_count = 0;
            __threadfence();
            atomicExch(&g_bar_gen, my + 1u);
        } else {
            while (*(volatile unsigned*)&g_bar_gen == my) { }
        }
        __threadfence();
    }
    __syncthreads();
}

// ---------------------------------------------------------------------------
// Init kernels (per replay; deterministic)
// ---------------------------------------------------------------------------
__device__ __forceinline__ void split_store(float v, unsigned char* hi_ptr,
                                            unsigned lo_delta) {
    __nv_bfloat16 h = __float2bfloat16(v);
    __nv_bfloat16 l = __float2bfloat16(v - __bfloat162float(h));
    *(__nv_bfloat16*)hi_ptr = h;
    *(__nv_bfloat16*)(hi_ptr + lo_delta) = l;
}

__global__ void init_state_kernel() {
    int i = blockIdx.x * blockDim.x + threadIdx.x;
    if (i < (32 * 16384) / 4) {
        ((unsigned*)g_h0t)[i] = 0u;
        ((unsigned*)g_h1t)[i] = 0u;
    }
    if (i < BQ * HQ) { g_c0[i] = 0.f; g_c1[i] = 0.f; }
}
__global__ void init_x_kernel(const float* __restrict__ x) {
    int i = blockIdx.x * blockDim.x + threadIdx.x;   // = b*32768 + t*128 + k
    if (i >= BQ * TQ * INQ) return;
    int k = i & 127, t = (i >> 7) & 255, b = i >> 15;
    int u = k >> 5, kl = k & 31;
    unsigned char* dst = g_xt + (size_t)(t * 4 + u) * TILE16K + off_in_tile(b, kl);
    split_store(x[i], dst, 8192u);
}
__global__ void init_w_kernel(
    const float* __restrict__ W_ih0, const float* __restrict__ W_hh0,
    const float* __restrict__ W_ih1, const float* __restrict__ W_hh1)
{
    // 64-row W tiles: row r -> gate col (r>>4)*1024 + tile*16 + (r&15)
    const unsigned N0 = 64u * NU0 * 2048u;   // hi elements in W0
    const unsigned N1 = 64u * 64u * 2048u;
    for (unsigned i = blockIdx.x * blockDim.x + threadIdx.x; i < N0 + N1;
         i += gridDim.x * blockDim.x) {
        if (i < N0) {
            unsigned kl = i & 31u, r = (i >> 5) & 63u;
            unsigned rest = i >> 11, u = rest % NU0, tile = rest / NU0;
            unsigned gcol = ((r >> 4) << 10) + tile * 16u + (r & 15u);
            unsigned k = u * 32u + kl;
            float v = (k < 128u) ? W_ih0[(size_t)gcol * 128u + k]
                                 : W_hh0[(size_t)gcol * 1024u + (k - 128u)];
            split_store(v, g_W0t + (size_t)(tile * NU0 + u) * TILEW
                            + off_in_tile(r, kl), 4096u);
        } else {
            unsigned j = i - N0;
            unsigned kl = j & 31u, r = (j >> 5) & 63u;
            unsigned rest = j >> 11, u = rest & 63u, tile = rest >> 6;
            unsigned gcol = ((r >> 4) << 10) + tile * 16u + (r & 15u);
            unsigned k = u * 32u + kl;
            float v = (k < 1024u) ? W_ih1[(size_t)gcol * 1024u + k]
                                  : W_hh1[(size_t)gcol * 1024u + (k - 1024u)];
            split_store(v, g_W1t + (size_t)(tile * 64u + u) * TILEW
                            + off_in_tile(r, kl), 4096u);
        }
    }
}

// ---------------------------------------------------------------------------
// One cell-slice (1/4 of the cell update) on all threads of all CTAs.
// part layout [slot][b][4096] -> fully coalesced reads.
// ---------------------------------------------------------------------------
template <int NS>
__device__ __forceinline__ void cell_slice(
    int it, float* __restrict__ cst, unsigned char* __restrict__ htile,
    float* __restrict__ hf, const float* __restrict__ part,
    const float* __restrict__ b_ih, const float* __restrict__ b_hh)
{
    int gid  = blockIdx.x * NTHR + threadIdx.x + it * NCTA * NTHR;  // b*1024+n
    int n    = gid & 1023;
    int b    = gid >> 10;
    int tl   = n >> 5, nl = n & 31;   // A-tile (h) indexing: 32 tiles of 32

    float g4[4];
    #pragma unroll
    for (int g = 0; g < 4; ++g) {
        float sum = b_ih[g * 1024 + n] + b_hh[g * 1024 + n];
        #pragma unroll
        for (int s2 = 0; s2 < NS; ++s2)
            sum += part[((size_t)(s2 * 128 + b) << 12) + g * 1024 + n];
        g4[g] = sum;
    }
    float si = 1.f / (1.f + expf(-g4[0]));
    float sf = 1.f / (1.f + expf(-g4[1]));
    float so = 1.f / (1.f + expf(-g4[3]));
    float cn = sf * cst[gid] + si * tanhf(g4[2]);
    cst[gid] = cn;
    float hv = so * tanhf(cn);
    split_store(hv, htile + (size_t)tl * TILE16K + off_in_tile(b, nl), 8192u);
    if (hf) hf[gid] = hv;
}

// ---------------------------------------------------------------------------
// GEMM phase: CTA computes 128(batch) x 64(gate-col) partial. 4 warps in
// 2(M) x 2(N); warp tile 64x32; per unit 96 HMMAs/warp (3-term split bf16,
// term-outer). Cell slices (CELLK: 0 none, 1 cell0, 2 cell1) interleaved.
// ---------------------------------------------------------------------------
template <int CELLK>
__device__ void gemm_phase(
    const unsigned char* __restrict__ pxa, int uxsplit,
    const unsigned char* __restrict__ pha,
    const unsigned char* __restrict__ pw,
    int ulo, int nU, float* __restrict__ pslot,   // + b*4096 + (c>>4)*1024 + c&15
    unsigned sb, unsigned* ph, bool docell,
    const float* b_ih, const float* b_hh)
{
    const int tid  = threadIdx.x;
    const int lane = tid & 31;
    const int wid  = tid >> 5;
    const int wm   = wid >> 1;   // 0..1
    const int wn   = wid & 1;    // 0..1

    float acc[4][4][4];
    #pragma unroll
    for (int m = 0; m < 4; ++m)
        #pragma unroll
        for (int n = 0; n < 4; ++n)
            #pragma unroll
            for (int r = 0; r < 4; ++r) acc[m][n][r] = 0.f;

    auto issue = [&](int idx) {
        int u = ulo + idx;
        const unsigned char* asrc = (u < uxsplit)
            ? pxa + (size_t)u * TILE16K
            : pha + (size_t)(u - uxsplit) * TILE16K;
        const unsigned char* wsrc = pw + (size_t)u * TILEW;
        int buf = idx & (NBUF - 1);
        unsigned mbar = sb + (unsigned)buf * 8u;
        unsigned dst  = sb + 1024u + (unsigned)buf * STAGEB;
        mbar_expect_tx(mbar, STAGEB);
        bulk_g2s(dst,           asrc, TILE16K, mbar);
        bulk_g2s(dst + TILE16K, wsrc, TILEW,   mbar);
    };

    if (tid == 0) {
        int np = nU < NBUF ? nU : NBUF;
        for (int p = 0; p < np; ++p) issue(p);
    }

    for (int i = 0; i < nU; ++i) {
        int buf = i & (NBUF - 1);
        mbar_wait(sb + (unsigned)buf * 8u, ph[buf]);
        ph[buf] ^= 1u;
        unsigned bA = sb + 1024u + (unsigned)buf * STAGEB;   // A hi (lo +8192)
        unsigned bW = bA + TILE16K;                          // W hi (lo +4096)

        #pragma unroll
        for (int j = 0; j < 2; ++j) {
            // A fragments: 4 m-tiles x (hi,lo)
            int rA = wm * 64 + (lane & 15);
            unsigned aH = bA + (unsigned)(rA * 64)
                        + ((unsigned)((j * 2 + (lane >> 4)) ^ ((rA >> 1) & 3)) << 4);
            unsigned AH[4][4], AL[4][4];
            #pragma unroll
            for (int m = 0; m < 4; ++m) {
                ldsm4(AH[m][0], AH[m][1], AH[m][2], AH[m][3], aH + m * 1024u);
                ldsm4(AL[m][0], AL[m][1], AL[m][2], AL[m][3], aH + m * 1024u + 8192u);
            }
            // W fragments: 2 ldsm4 per (hi,lo); covers n-pair per ldsm4
            unsigned WH[4][2], WL[4][2];
            #pragma unroll
            for (int np = 0; np < 2; ++np) {
                int nn = np * 2 + (lane >> 4);
                int rW = wn * 32 + nn * 8 + (lane & 7);
                unsigned wAddr = bW + (unsigned)(rW * 64)
                    + ((unsigned)((j * 2 + ((lane >> 3) & 1)) ^ ((rW >> 1) & 3)) << 4);
                ldsm4(WH[np*2][0], WH[np*2][1], WH[np*2+1][0], WH[np*2+1][1], wAddr);
                ldsm4(WL[np*2][0], WL[np*2][1], WL[np*2+1][0], WL[np*2+1][1],
                      wAddr + 4096u);
            }
            if (j == 1) {
                __syncthreads();     // all 128 threads done reading this buffer
                if (tid == 0 && i + NBUF < nU) issue(i + NBUF);
            }
            // Term-outer MMA: consecutive MMAs hit different accumulators
            #pragma unroll
            for (int m = 0; m < 4; ++m)
                #pragma unroll
                for (int n = 0; n < 4; ++n)
                    mma16816(acc[m][n], AH[m], WH[n]);
            #pragma unroll
            for (int m = 0; m < 4; ++m)
                #pragma unroll
                for (int n = 0; n < 4; ++n)
                    mma16816(acc[m][n], AL[m], WH[n]);
            #pragma unroll
            for (int m = 0; m < 4; ++m)
                #pragma unroll
                for (int n = 0; n < 4; ++n)
                    mma16816(acc[m][n], AH[m], WL[n]);
        }

        if (CELLK == 2 && docell && (i & 1) == 0 && i < 8)
            cell_slice<8>(i >> 1, g_c1, g_h1t, g_h1f, g_part1, b_ih, b_hh);
        else if (CELLK == 1 && docell && (i & 1) == 0 && i < 8)
            cell_slice<4>(i >> 1, g_c0, g_h0t, nullptr, g_part0, b_ih, b_hh);
    }

    // Epilogue: D fragments -> pslot (gate-decomposed columns)
    #pragma unroll
    for (int m = 0; m < 4; ++m)
        #pragma unroll
        for (int n = 0; n < 4; ++n) {
            int b = wm * 64 + m * 16 + (lane >> 2);
            int c = wn * 32 + n * 8 + (lane & 3) * 2;   // 0..63
            size_t off = (size_t)b * 4096 + (size_t)(c >> 4) * 1024 + (c & 15);
            *(float2*)(pslot + off) =
                make_float2(acc[m][n][0], acc[m][n][1]);
            *(float2*)(pslot + off + 8 * 4096) =
                make_float2(acc[m][n][2], acc[m][n][3]);
        }
}

// ---------------------------------------------------------------------------
// Main persistent kernel: 3 phases per step; 2 CTAs/SM overlap each other's
// latency. CTA -> (tile = cta & 63, s = cta >> 6).
// ---------------------------------------------------------------------------
__global__ __launch_bounds__(NTHR, 2) void lstm_mma_kernel(
    const float* __restrict__ b_ih0, const float* __restrict__ b_hh0,
    const float* __restrict__ b_ih1, const float* __restrict__ b_hh1,
    const float* __restrict__ Wd,    const float* __restrict__ bd,
    float* __restrict__ out)
{
    extern __shared__ __align__(1024) unsigned char dsmem[];
    const unsigned sb = smem_u32(dsmem);
    const int tid  = threadIdx.x;
    const int cta  = blockIdx.x;
    const int tile = cta & 63;
    const int s    = cta >> 6;

    if (tid == 0) {
        #pragma unroll
        for (int i = 0; i < NBUF; ++i) mbar_init(sb + i * 8u, 1u);
        fence_async();
    }
    __syncthreads();

    unsigned ph[NBUF] = {0, 0, 0, 0};

    const unsigned char* w0 = g_W0t + (size_t)tile * NU0 * TILEW;
    const unsigned char* w1 = g_W1t + (size_t)tile * 64u * TILEW;
    // slot bases: + tile's 16-col group start (c>>4 handles gate offset)
    float* p0slot  = g_part0 + ((size_t)s << 19) + tile * 16;          // [s][b][..]
    float* p1aslot = g_part1 + ((size_t)s << 19) + tile * 16;
    float* p1bslot = g_part1 + ((size_t)(4 + s) << 19) + tile * 16;

    for (int t = 0; t < TQ; ++t) {
        // P1: gemm0(t) [9 units: x(0-3), h0(4-35)] + interleaved cell1(t-1)
        gemm_phase<2>(g_xt + (size_t)t * 4 * TILE16K, 4, g_h0t, w0,
                      s * 9, 9, p0slot, sb, ph, t > 0, b_ih1, b_hh1);
        grid_bar();

        // P2: gemm1 h1-half [units 32+s*8..+8, A = h1] + interleaved cell0(t)
        gemm_phase<1>(nullptr, 32, g_h1t, w1,
                      32 + s * 8, 8, p1aslot, sb, ph, true, b_ih0, b_hh0);
        grid_bar();

        // P3: gemm1 h0-half [units s*8..+8, A = h0], no cell
        gemm_phase<0>(nullptr, 0, g_h0t, w1,
                      s * 8, 8, p1bslot, sb, ph, false, nullptr, nullptr);
        grid_bar();
    }

    // Final cell1(255) on all threads
    #pragma unroll
    for (int it = 0; it < 4; ++it)
        cell_slice<8>(it, g_c1, g_h1t, g_h1f, g_part1, b_ih1, b_hh1);
    grid_bar();

    // Dense head: CTAs 0..127 compute out[b][0..1] from fp32 h1
    if (cta < BQ) {
        float* red = (float*)dsmem;
        const int b = cta;
        float s0 = 0.f, s1 = 0.f;
        for (int n = tid; n < HQ; n += NTHR) {
            float hv = g_h1f[(size_t)b * HQ + n];
            s0 += hv * Wd[n];
            s1 += hv * Wd[HQ + n];
        }
        __syncthreads();
        red[tid] = s0; red[NTHR + tid] = s1;
        __syncthreads();
        for (int off = NTHR / 2; off > 0; off >>= 1) {
            if (tid < off) {
                red[tid] += red[tid + off];
                red[NTHR + tid] += red[NTHR + tid + off];
            }
            __syncthreads();
        }
        if (tid == 0) {
            out[b * 2 + 0] = tanhf(red[0] + bd[0]);
            out[b * 2 + 1] = tanhf(red[NTHR] + bd[1]);
        }
    }
}

// ---------------------------------------------------------------------------
// Launch: 4 graph nodes
// ---------------------------------------------------------------------------
extern "C" void kernel_launch(void* const* d_in, const int* in_sizes, int n_in,
                              void* d_out, int out_size)
{
    const float* x     = (const float*)d_in[0];
    const float* W_ih0 = (const float*)d_in[1];
    const float* W_hh0 = (const float*)d_in[2];
    const float* b_ih0 = (const float*)d_in[3];
    const float* b_hh0 = (const float*)d_in[4];
    const float* W_ih1 = (const float*)d_in[5];
    const float* W_hh1 = (const float*)d_in[6];
    const float* b_ih1 = (const float*)d_in[7];
    const float* b_hh1 = (const float*)d_in[8];
    const float* Wd    = (const float*)d_in[9];
    const float* bd    = (const float*)d_in[10];
    float* out = (float*)d_out;

    const int smem_bytes = 1024 + NBUF * (int)STAGEB;   // 99328 -> 2 CTAs/SM
    cudaFuncSetAttribute(lstm_mma_kernel,
                         cudaFuncAttributeMaxDynamicSharedMemorySize, smem_bytes);

    init_state_kernel<<<(32 * 16384 / 4 + 255) / 256, 256>>>();
    init_x_kernel<<<(BQ * TQ * INQ + 255) / 256, 256>>>(x);
    init_w_kernel<<<2048, 256>>>(W_ih0, W_hh0, W_ih1, W_hh1);

    lstm_mma_kernel<<<NCTA, NTHR, smem_bytes>>>(
        b_ih0, b_hh0, b_ih1, b_hh1, Wd, bd, out);
}